// round 14
// baseline (speedup 1.0000x reference)
#include <cuda_runtime.h>
#include <cuda_fp16.h>
#include <cstdint>

#define H       128
#define MAXN    200000
#define MAXE    600000
#define NTYPES  16

#define SXH     136              // halves per smem row (128 + 8 pad)
#define SXB     (SXH * 2)        // 272 bytes per row -> conflict-free ldmatrix
#define STGB    544              // fp32 stage row bytes (512 + 32 pad)
#define XBUF    (128 * SXB)      // one fp16 X buffer

// smem layout (bytes) for GEMM
#define SM_BIAS  0                           // 128 floats = 512B
#define SM_STAGE 512                         // fp32 X tile: 128 x 544B = 69632B
#define SM_X0    (SM_STAGE + 128 * STGB)     // fp16 X buf0 + buf1: 2 x 34816B
#define SM_W     (SM_X0 + 2 * XBUF)          // W: 256 x 272B = 69632B
#define SM_TOT   (SM_W + 256 * SXB)          // 209,408B

// ---------------- scratch (static device arrays) ----------------
__device__ __align__(256) __half g_acc[(size_t)MAXN * H];   // self-half (+biases), fp16
__device__ __align__(256) __half g_y[(size_t)MAXN * H];     // y = x @ W_msg^T (fp16)
__device__ __align__(256) float  g_emb2[NTYPES * H];        // edge_emb @ W_msg^T
__device__ int g_deg[MAXN];
__device__ int g_start[MAXN];
__device__ int g_cursor[MAXN];
__device__ int g_pk[MAXE];                                  // packed src | type<<24
__device__ int g_total;

__device__ __forceinline__ uint32_t smem_u32(const void* p) {
    uint32_t a;
    asm("{ .reg .u64 t; cvta.to.shared.u64 t, %1; cvt.u32.u64 %0, t; }" : "=r"(a) : "l"(p));
    return a;
}

__device__ __forceinline__ void ldmx4(uint32_t* r, uint32_t addr) {
    asm volatile("ldmatrix.sync.aligned.m8n8.x4.shared.b16 {%0,%1,%2,%3}, [%4];"
                 : "=r"(r[0]), "=r"(r[1]), "=r"(r[2]), "=r"(r[3]) : "r"(addr));
}

__device__ __forceinline__ void mma_f32(float* c, const uint32_t* a, uint32_t b0, uint32_t b1) {
    asm volatile("mma.sync.aligned.m16n8k16.row.col.f32.f16.f16.f32 "
                 "{%0,%1,%2,%3}, {%4,%5,%6,%7}, {%8,%9}, {%0,%1,%2,%3};"
                 : "+f"(c[0]), "+f"(c[1]), "+f"(c[2]), "+f"(c[3])
                 : "r"(a[0]), "r"(a[1]), "r"(a[2]), "r"(a[3]), "r"(b0), "r"(b1));
}

__device__ __forceinline__ void cpasync16(uint32_t saddr, const void* gptr) {
    asm volatile("cp.async.cg.shared.global [%0], [%1], 16;"
                 :: "r"(saddr), "l"(gptr) : "memory");
}
#define CP_COMMIT() asm volatile("cp.async.commit_group;" ::: "memory")
#define CP_WAIT0()  asm volatile("cp.async.wait_group 0;" ::: "memory")

__device__ __forceinline__ uint32_t h2u(__half2 h) { return *reinterpret_cast<uint32_t*>(&h); }
__device__ __forceinline__ __half2 u2h(uint32_t u) { return *reinterpret_cast<__half2*>(&u); }

// streaming (evict-first) 16B store
__device__ __forceinline__ void stcs16(void* p, uint4 v) {
    asm volatile("st.global.cs.v4.b32 [%0], {%1,%2,%3,%4};"
                 :: "l"(p), "r"(v.x), "r"(v.y), "r"(v.z), "r"(v.w) : "memory");
}
__device__ __forceinline__ void stcs16f(void* p, float4 v) {
    asm volatile("st.global.cs.v4.f32 [%0], {%1,%2,%3,%4};"
                 :: "l"(p), "f"(v.x), "f"(v.y), "f"(v.z), "f"(v.w) : "memory");
}
// streaming 16B load
__device__ __forceinline__ uint4 ldcs16(const void* p) {
    uint4 v;
    asm volatile("ld.global.cs.v4.b32 {%0,%1,%2,%3}, [%4];"
                 : "=r"(v.x), "=r"(v.y), "=r"(v.z), "=r"(v.w) : "l"(p));
    return v;
}
__device__ __forceinline__ int ldcs_i(const int* p) {
    int v;
    asm volatile("ld.global.cs.s32 %0, [%1];" : "=r"(v) : "l"(p));
    return v;
}

// ---------------------------------------------------------------------------
// Init: zero g_deg/g_total; blocks 0..15 also compute emb2 = edge_emb @ W_msg^T
// ---------------------------------------------------------------------------
__global__ __launch_bounds__(1024)
void init_kernel(const float* __restrict__ emb, const float* __restrict__ Wm, int N) {
    int i = blockIdx.x * 1024 + threadIdx.x;
    if (i < N) g_deg[i] = 0;
    if (i == 0) g_total = 0;

    if (blockIdx.x < NTYPES && threadIdx.x < H) {
        int r = blockIdx.x, j = threadIdx.x;
        const float4* e4 = (const float4*)(emb + r * H);
        const float4* w4 = (const float4*)(Wm + j * H);
        float s = 0.f;
        #pragma unroll
        for (int k = 0; k < H / 4; k++) {
            float4 a = e4[k], b = w4[k];
            s += a.x * b.x + a.y * b.y + a.z * b.z + a.w * b.w;
        }
        g_emb2[r * H + j] = s;
    }
}

// ---------------------------------------------------------------------------
// Tensor-core GEMM (persistent, pipelined; R13 structure + streaming g_acc store)
// ---------------------------------------------------------------------------
__global__ __launch_bounds__(1024, 1)
void gemm_tc_kernel(const float* __restrict__ x,
                    const float* __restrict__ Wself,
                    const float* __restrict__ Wmsg,
                    const float* __restrict__ bself,
                    const float* __restrict__ bmsg,
                    int N) {
    extern __shared__ char smem[];
    const uint32_t sb = smem_u32(smem);
    float* s_bias = (float*)(smem + SM_BIAS);

    const int tid  = threadIdx.x;
    const int wid  = tid >> 5, lane = tid & 31;
    const int wm   = (wid >> 3) * 32;
    const int wn   = (wid & 7) * 32;

    if (tid < H) s_bias[tid] = bself[tid] + bmsg[tid];

    // ---- W (fp16) into smem, once ----
    {
        const int n  = tid >> 2;
        const int kq = (tid & 3) * 32;
        const float* wrow = (n < H) ? (Wself + (size_t)n * H) : (Wmsg + (size_t)(n - H) * H);
        const float4* w4 = (const float4*)(wrow + kq);
        char* dst = smem + SM_W + n * SXB + kq * 2;
        #pragma unroll
        for (int i = 0; i < 8; i++) {
            float4 v = w4[i];
            __half2 h0 = __float22half2_rn(make_float2(v.x, v.y));
            __half2 h1 = __float22half2_rn(make_float2(v.z, v.w));
            *reinterpret_cast<uint2*>(dst + i * 8) = make_uint2(h2u(h0), h2u(h1));
        }
    }

    const int ntiles = (N + 127) >> 7;
    const int gsz    = gridDim.x;

    const int sr  = tid >> 3;
    const int cof = (tid & 7) * 16;

    const uint32_t stS = sb + SM_STAGE + sr * STGB + cof;
    const char*    stC = smem + SM_STAGE + sr * STGB + cof;
    char*          xd0 = smem + SM_X0 + sr * SXB + cof / 2;

    const uint32_t aB = sb + SM_X0 + (wm + (lane & 15)) * SXB + (lane >> 4) * 16;
    const uint32_t bB = sb + SM_W  + (wn + (lane & 15)) * SXB + (lane >> 4) * 16;

    // ---- prologue: fetch t0, convert into X[0], fetch t1 ----
    {
        int t0 = blockIdx.x;
        if (t0 < ntiles) {
            int gr = (t0 << 7) + sr; if (gr > N - 1) gr = N - 1;
            const char* gp = (const char*)(x + (size_t)gr * H) + cof;
            #pragma unroll
            for (int i = 0; i < 4; i++) cpasync16(stS + i * 128, gp + i * 128);
        }
        CP_COMMIT();
        CP_WAIT0();
        #pragma unroll
        for (int i = 0; i < 4; i++) {
            float4 v = *reinterpret_cast<const float4*>(stC + i * 128);
            __half2 h0 = __float22half2_rn(make_float2(v.x, v.y));
            __half2 h1 = __float22half2_rn(make_float2(v.z, v.w));
            *reinterpret_cast<uint2*>(xd0 + i * 64) = make_uint2(h2u(h0), h2u(h1));
        }
        __syncthreads();
        int t1 = t0 + gsz;
        if (t1 < ntiles) {
            int gr = (t1 << 7) + sr; if (gr > N - 1) gr = N - 1;
            const char* gp = (const char*)(x + (size_t)gr * H) + cof;
            #pragma unroll
            for (int i = 0; i < 4; i++) cpasync16(stS + i * 128, gp + i * 128);
        }
        CP_COMMIT();
    }

    int cur = 0;
    for (int t = blockIdx.x; t < ntiles; t += gsz) {
        const int row0 = t << 7;

        CP_WAIT0();

        char* xdn = xd0 + (cur ^ 1) * XBUF;

        float acc[2][4][4];
        #pragma unroll
        for (int mt = 0; mt < 2; mt++)
            #pragma unroll
            for (int nt = 0; nt < 4; nt++)
                #pragma unroll
                for (int j = 0; j < 4; j++) acc[mt][nt][j] = 0.f;

        const uint32_t aT = aB + cur * XBUF;
        #pragma unroll
        for (int ks = 0; ks < 8; ks++) {
            if (ks < 4) {
                float4 v = *reinterpret_cast<const float4*>(stC + ks * 128);
                __half2 h0 = __float22half2_rn(make_float2(v.x, v.y));
                __half2 h1 = __float22half2_rn(make_float2(v.z, v.w));
                *reinterpret_cast<uint2*>(xdn + ks * 64) = make_uint2(h2u(h0), h2u(h1));
            }
            const uint32_t ko = ks * 32;
            uint32_t a0[4], a1[4], b0[4], b1[4];
            ldmx4(a0, aT + ko);
            ldmx4(a1, aT + 16 * SXB + ko);
            ldmx4(b0, bB + ko);
            ldmx4(b1, bB + 16 * SXB + ko);
            mma_f32(acc[0][0], a0, b0[0], b0[2]);
            mma_f32(acc[0][1], a0, b0[1], b0[3]);
            mma_f32(acc[0][2], a0, b1[0], b1[2]);
            mma_f32(acc[0][3], a0, b1[1], b1[3]);
            mma_f32(acc[1][0], a1, b0[0], b0[2]);
            mma_f32(acc[1][1], a1, b0[1], b0[3]);
            mma_f32(acc[1][2], a1, b1[0], b1[2]);
            mma_f32(acc[1][3], a1, b1[1], b1[3]);
        }

        __syncthreads();

        // ---- prefetch stage <- tile t+2 (overlaps epilogue) ----
        {
            int nt2 = t + 2 * gsz;
            if (nt2 < ntiles) {
                int gr = (nt2 << 7) + sr; if (gr > N - 1) gr = N - 1;
                const char* gp = (const char*)(x + (size_t)gr * H) + cof;
                #pragma unroll
                for (int i = 0; i < 4; i++) cpasync16(stS + i * 128, gp + i * 128);
            }
            CP_COMMIT();
        }

        // ---- epilogue: stage halves into X[cur] (dead), coalesced STG ----
        const bool self_half = (wn < H);
        const int cb2 = (self_half ? wn : wn - H) + (lane & 3) * 2;
        char* stage = smem + SM_X0 + cur * XBUF;

        #pragma unroll
        for (int hp = 0; hp < 2; hp++) {
            if (hp) __syncthreads();
            if (self_half == (hp == 0)) {
                #pragma unroll
                for (int mt = 0; mt < 2; mt++) {
                    const int rr = wm + mt * 16 + (lane >> 2);
                    #pragma unroll
                    for (int nt = 0; nt < 4; nt++) {
                        const int cc = cb2 + nt * 8;
                        float2 v0 = make_float2(acc[mt][nt][0], acc[mt][nt][1]);
                        float2 v1 = make_float2(acc[mt][nt][2], acc[mt][nt][3]);
                        if (self_half) {
                            float2 b2 = *(const float2*)&s_bias[cc];
                            v0.x += b2.x; v0.y += b2.y;
                            v1.x += b2.x; v1.y += b2.y;
                        }
                        *(__half2*)(stage + rr * SXB + cc * 2)       = __float22half2_rn(v0);
                        *(__half2*)(stage + (rr + 8) * SXB + cc * 2) = __float22half2_rn(v1);
                    }
                }
            }
            __syncthreads();
            // cooperative coalesced store: g_acc (hp=0) streaming, g_y (hp=1) cached
            {
                const int r  = tid >> 3;
                const int ch = (tid & 7) * 32;
                const int grow = row0 + r;
                if (grow < N) {
                    uint4 d0 = *(const uint4*)(stage + r * SXB + ch);
                    uint4 d1 = *(const uint4*)(stage + r * SXB + ch + 16);
                    if (hp == 0) {
                        char* da = (char*)(g_acc + (size_t)grow * H) + ch;
                        stcs16(da, d0);
                        stcs16(da + 16, d1);
                    } else {
                        char* dy = (char*)(g_y + (size_t)grow * H) + ch;
                        *(uint4*)dy        = d0;
                        *(uint4*)(dy + 16) = d1;
                    }
                }
            }
        }
        __syncthreads();

        cur ^= 1;
    }
}

// ---------------------------------------------------------------------------
// CSR build
// ---------------------------------------------------------------------------
__global__ __launch_bounds__(512)
void hist_kernel(const int* __restrict__ ei, int E) {
    int i = blockIdx.x * 512 + threadIdx.x;
    int stride = gridDim.x * 512;
    for (int e = i; e < E; e += stride)
        atomicAdd(&g_deg[ei[E + e]], 1);
}

__global__ __launch_bounds__(256)
void assign_kernel(int N) {
    const int n    = blockIdx.x * 256 + threadIdx.x;
    const int lane = threadIdx.x & 31;
    int d = (n < N) ? g_deg[n] : 0;
    int s = d;
    #pragma unroll
    for (int o = 1; o < 32; o <<= 1) {
        int t = __shfl_up_sync(0xffffffffu, s, o);
        if (lane >= o) s += t;
    }
    int base = 0;
    if (lane == 31) base = atomicAdd(&g_total, s);
    base = __shfl_sync(0xffffffffu, base, 31);
    if (n < N) {
        int st = base + s - d;
        g_start[n]  = st;
        g_cursor[n] = st;
    }
}

__global__ __launch_bounds__(512)
void fill_kernel(const int* __restrict__ ei, const int* __restrict__ et, int E) {
    int i = blockIdx.x * 512 + threadIdx.x;
    int stride = gridDim.x * 512;
    for (int e = i; e < E; e += stride) {
        int src = ei[e];
        int dst = ei[E + e];
        int ty  = et[e];
        int slot = atomicAdd(&g_cursor[dst], 1);
        g_pk[slot] = src | (ty << 24);
    }
}

// ---------------------------------------------------------------------------
// Fused aggregate + ReLU + LayerNorm: one HALF-WARP (16 lanes) per node row.
// Streaming hints: g_acc/g_pk reads + out stores evict-first; g_y stays in L2.
// ---------------------------------------------------------------------------
__global__ __launch_bounds__(256)
void aggregate_ln_kernel(const float* __restrict__ gamma, const float* __restrict__ beta,
                         float* __restrict__ out, int N) {
    __shared__ float s_emb[NTYPES * H];
    for (int i = threadIdx.x; i < NTYPES * H; i += 256) s_emb[i] = g_emb2[i];
    __syncthreads();

    const int lane16 = threadIdx.x & 15;
    const int row    = blockIdx.x * 16 + (threadIdx.x >> 4);
    if (row >= N) return;
    const int off = lane16 * 8;    // 8 halves

    float v[8];
    {
        uint4 a = ldcs16(&g_acc[(size_t)row * H + off]);
        float2 f0 = __half22float2(u2h(a.x)), f1 = __half22float2(u2h(a.y));
        float2 f2 = __half22float2(u2h(a.z)), f3 = __half22float2(u2h(a.w));
        v[0] = f0.x; v[1] = f0.y; v[2] = f1.x; v[3] = f1.y;
        v[4] = f2.x; v[5] = f2.y; v[6] = f3.x; v[7] = f3.y;
    }

    const int st = __ldg(&g_start[row]);
    const int en = st + __ldg(&g_deg[row]);
    int i = st;
    for (; i + 2 <= en; i += 2) {
        int p0 = ldcs_i(&g_pk[i]), p1 = ldcs_i(&g_pk[i + 1]);
        int s0 = p0 & 0xFFFFFF, t0 = p0 >> 24;
        int s1 = p1 & 0xFFFFFF, t1 = p1 >> 24;
        uint4 m0 = __ldg((const uint4*)&g_y[(size_t)s0 * H + off]);
        uint4 m1 = __ldg((const uint4*)&g_y[(size_t)s1 * H + off]);
        float4 e0a = *(const float4*)&s_emb[t0 * H + off];
        float4 e0b = *(const float4*)&s_emb[t0 * H + off + 4];
        float4 e1a = *(const float4*)&s_emb[t1 * H + off];
        float4 e1b = *(const float4*)&s_emb[t1 * H + off + 4];
        float2 a0 = __half22float2(u2h(m0.x)), a1 = __half22float2(u2h(m0.y));
        float2 a2 = __half22float2(u2h(m0.z)), a3 = __half22float2(u2h(m0.w));
        float2 b0 = __half22float2(u2h(m1.x)), b1 = __half22float2(u2h(m1.y));
        float2 b2 = __half22float2(u2h(m1.z)), b3 = __half22float2(u2h(m1.w));
        v[0] += a0.x + e0a.x + b0.x + e1a.x;
        v[1] += a0.y + e0a.y + b0.y + e1a.y;
        v[2] += a1.x + e0a.z + b1.x + e1a.z;
        v[3] += a1.y + e0a.w + b1.y + e1a.w;
        v[4] += a2.x + e0b.x + b2.x + e1b.x;
        v[5] += a2.y + e0b.y + b2.y + e1b.y;
        v[6] += a3.x + e0b.z + b3.x + e1b.z;
        v[7] += a3.y + e0b.w + b3.y + e1b.w;
    }
    if (i < en) {
        int p0 = ldcs_i(&g_pk[i]);
        int s0 = p0 & 0xFFFFFF, t0 = p0 >> 24;
        uint4 m0 = __ldg((const uint4*)&g_y[(size_t)s0 * H + off]);
        float4 e0a = *(const float4*)&s_emb[t0 * H + off];
        float4 e0b = *(const float4*)&s_emb[t0 * H + off + 4];
        float2 a0 = __half22float2(u2h(m0.x)), a1 = __half22float2(u2h(m0.y));
        float2 a2 = __half22float2(u2h(m0.z)), a3 = __half22float2(u2h(m0.w));
        v[0] += a0.x + e0a.x; v[1] += a0.y + e0a.y;
        v[2] += a1.x + e0a.z; v[3] += a1.y + e0a.w;
        v[4] += a2.x + e0b.x; v[5] += a2.y + e0b.y;
        v[6] += a3.x + e0b.z; v[7] += a3.y + e0b.w;
    }

    float s = 0.f, sq = 0.f;
    #pragma unroll
    for (int j = 0; j < 8; j++) {
        v[j] = fmaxf(v[j], 0.f);
        s  += v[j];
        sq += v[j] * v[j];
    }
    #pragma unroll
    for (int o = 8; o > 0; o >>= 1) {
        s  += __shfl_xor_sync(0xffffffffu, s,  o);
        sq += __shfl_xor_sync(0xffffffffu, sq, o);
    }
    float mean = s * (1.f / H);
    float var  = sq * (1.f / H) - mean * mean;
    float rstd = rsqrtf(var + 1e-5f);

    float4 ga = *(const float4*)&gamma[off];
    float4 gb = *(const float4*)&gamma[off + 4];
    float4 ba = *(const float4*)&beta[off];
    float4 bb = *(const float4*)&beta[off + 4];
    float4 o0, o1;
    o0.x = (v[0] - mean) * rstd * ga.x + ba.x;
    o0.y = (v[1] - mean) * rstd * ga.y + ba.y;
    o0.z = (v[2] - mean) * rstd * ga.z + ba.z;
    o0.w = (v[3] - mean) * rstd * ga.w + ba.w;
    o1.x = (v[4] - mean) * rstd * gb.x + bb.x;
    o1.y = (v[5] - mean) * rstd * gb.y + bb.y;
    o1.z = (v[6] - mean) * rstd * gb.z + bb.z;
    o1.w = (v[7] - mean) * rstd * gb.w + bb.w;
    stcs16f(&out[(size_t)row * H + off],     o0);
    stcs16f(&out[(size_t)row * H + off + 4], o1);
}

// ---------------------------------------------------------------------------
extern "C" void kernel_launch(void* const* d_in, const int* in_sizes, int n_in,
                              void* d_out, int out_size) {
    const float* x     = (const float*)d_in[0];
    const int*   ei    = (const int*)  d_in[1];
    const int*   et    = (const int*)  d_in[2];
    const float* emb   = (const float*)d_in[3];
    const float* Wself = (const float*)d_in[4];
    const float* bself = (const float*)d_in[5];
    const float* Wmsg  = (const float*)d_in[6];
    const float* bmsg  = (const float*)d_in[7];
    const float* gamma = (const float*)d_in[8];
    const float* beta  = (const float*)d_in[9];
    float* out = (float*)d_out;

    const int N = in_sizes[0] / H;
    const int E = in_sizes[1] / 2;

    cudaFuncSetAttribute(gemm_tc_kernel, cudaFuncAttributeMaxDynamicSharedMemorySize, SM_TOT);

    // gemm_tc_kernel kept at absolute launch index 3 (the slot ncu samples).
    init_kernel<<<(N + 1023) / 1024, 1024>>>(emb, Wmsg, N);
    hist_kernel<<<592, 512>>>(ei, E);
    assign_kernel<<<(N + 255) / 256, 256>>>(N);
    gemm_tc_kernel<<<152, 1024, SM_TOT>>>(x, Wself, Wmsg, bself, bmsg, N);
    fill_kernel<<<592, 512>>>(ei, et, E);
    aggregate_ln_kernel<<<(N + 15) / 16, 256>>>(gamma, beta, out, N);
}

// round 16
// speedup vs baseline: 1.0281x; 1.0281x over previous
#include <cuda_runtime.h>
#include <cuda_fp16.h>
#include <cstdint>

#define H       128
#define MAXN    200000
#define MAXE    600000
#define NTYPES  16

#define SXH     136              // halves per smem row (128 + 8 pad)
#define SXB     (SXH * 2)        // 272 bytes per row -> conflict-free ldmatrix
#define STGB    544              // fp32 stage row bytes (512 + 32 pad)
#define XBUF    (128 * SXB)      // one fp16 X buffer

// smem layout (bytes) for GEMM
#define SM_BIAS  0                           // 128 floats = 512B
#define SM_STAGE 512                         // fp32 X tile: 128 x 544B = 69632B
#define SM_X0    (SM_STAGE + 128 * STGB)     // fp16 X buf0 + buf1: 2 x 34816B
#define SM_W     (SM_X0 + 2 * XBUF)          // W: 256 x 272B = 69632B
#define SM_TOT   (SM_W + 256 * SXB)          // 209,408B

// ---------------- scratch (static device arrays) ----------------
__device__ __align__(256) __half g_acc[(size_t)MAXN * H];   // self-half (+biases), fp16
__device__ __align__(256) __half g_y[(size_t)MAXN * H];     // y = x @ W_msg^T (fp16)
__device__ __align__(256) float  g_emb2[NTYPES * H];        // edge_emb @ W_msg^T
__device__ int g_deg[MAXN];
__device__ int g_start[MAXN];
__device__ int g_cursor[MAXN];
__device__ int g_pk[MAXE];                                  // packed src | type<<24
__device__ int g_total;

__device__ __forceinline__ uint32_t smem_u32(const void* p) {
    uint32_t a;
    asm("{ .reg .u64 t; cvta.to.shared.u64 t, %1; cvt.u32.u64 %0, t; }" : "=r"(a) : "l"(p));
    return a;
}

__device__ __forceinline__ void ldmx4(uint32_t* r, uint32_t addr) {
    asm volatile("ldmatrix.sync.aligned.m8n8.x4.shared.b16 {%0,%1,%2,%3}, [%4];"
                 : "=r"(r[0]), "=r"(r[1]), "=r"(r[2]), "=r"(r[3]) : "r"(addr));
}

__device__ __forceinline__ void mma_f32(float* c, const uint32_t* a, uint32_t b0, uint32_t b1) {
    asm volatile("mma.sync.aligned.m16n8k16.row.col.f32.f16.f16.f32 "
                 "{%0,%1,%2,%3}, {%4,%5,%6,%7}, {%8,%9}, {%0,%1,%2,%3};"
                 : "+f"(c[0]), "+f"(c[1]), "+f"(c[2]), "+f"(c[3])
                 : "r"(a[0]), "r"(a[1]), "r"(a[2]), "r"(a[3]), "r"(b0), "r"(b1));
}

__device__ __forceinline__ void cpasync16(uint32_t saddr, const void* gptr) {
    asm volatile("cp.async.cg.shared.global [%0], [%1], 16;"
                 :: "r"(saddr), "l"(gptr) : "memory");
}
#define CP_COMMIT() asm volatile("cp.async.commit_group;" ::: "memory")
#define CP_WAIT0()  asm volatile("cp.async.wait_group 0;" ::: "memory")

__device__ __forceinline__ uint32_t h2u(__half2 h) { return *reinterpret_cast<uint32_t*>(&h); }
__device__ __forceinline__ __half2 u2h(uint32_t u) { return *reinterpret_cast<__half2*>(&u); }

// streaming (evict-first) 16B store (fp32)
__device__ __forceinline__ void stcs16f(void* p, float4 v) {
    asm volatile("st.global.cs.v4.f32 [%0], {%1,%2,%3,%4};"
                 :: "l"(p), "f"(v.x), "f"(v.y), "f"(v.z), "f"(v.w) : "memory");
}
// streaming 16B load
__device__ __forceinline__ uint4 ldcs16(const void* p) {
    uint4 v;
    asm volatile("ld.global.cs.v4.b32 {%0,%1,%2,%3}, [%4];"
                 : "=r"(v.x), "=r"(v.y), "=r"(v.z), "=r"(v.w) : "l"(p));
    return v;
}
__device__ __forceinline__ int ldcs_i(const int* p) {
    int v;
    asm volatile("ld.global.cs.s32 %0, [%1];" : "=r"(v) : "l"(p));
    return v;
}

// ---------------------------------------------------------------------------
// Init: zero g_deg/g_total; blocks 0..15 also compute emb2 = edge_emb @ W_msg^T
// ---------------------------------------------------------------------------
__global__ __launch_bounds__(1024)
void init_kernel(const float* __restrict__ emb, const float* __restrict__ Wm, int N) {
    int i = blockIdx.x * 1024 + threadIdx.x;
    if (i < N) g_deg[i] = 0;
    if (i == 0) g_total = 0;

    if (blockIdx.x < NTYPES && threadIdx.x < H) {
        int r = blockIdx.x, j = threadIdx.x;
        const float4* e4 = (const float4*)(emb + r * H);
        const float4* w4 = (const float4*)(Wm + j * H);
        float s = 0.f;
        #pragma unroll
        for (int k = 0; k < H / 4; k++) {
            float4 a = e4[k], b = w4[k];
            s += a.x * b.x + a.y * b.y + a.z * b.z + a.w * b.w;
        }
        g_emb2[r * H + j] = s;
    }
}

// ---------------------------------------------------------------------------
// Tensor-core GEMM (persistent, pipelined; exact R13 structure)
// ---------------------------------------------------------------------------
__global__ __launch_bounds__(1024, 1)
void gemm_tc_kernel(const float* __restrict__ x,
                    const float* __restrict__ Wself,
                    const float* __restrict__ Wmsg,
                    const float* __restrict__ bself,
                    const float* __restrict__ bmsg,
                    int N) {
    extern __shared__ char smem[];
    const uint32_t sb = smem_u32(smem);
    float* s_bias = (float*)(smem + SM_BIAS);

    const int tid  = threadIdx.x;
    const int wid  = tid >> 5, lane = tid & 31;
    const int wm   = (wid >> 3) * 32;
    const int wn   = (wid & 7) * 32;

    if (tid < H) s_bias[tid] = bself[tid] + bmsg[tid];

    // ---- W (fp16) into smem, once ----
    {
        const int n  = tid >> 2;
        const int kq = (tid & 3) * 32;
        const float* wrow = (n < H) ? (Wself + (size_t)n * H) : (Wmsg + (size_t)(n - H) * H);
        const float4* w4 = (const float4*)(wrow + kq);
        char* dst = smem + SM_W + n * SXB + kq * 2;
        #pragma unroll
        for (int i = 0; i < 8; i++) {
            float4 v = w4[i];
            __half2 h0 = __float22half2_rn(make_float2(v.x, v.y));
            __half2 h1 = __float22half2_rn(make_float2(v.z, v.w));
            *reinterpret_cast<uint2*>(dst + i * 8) = make_uint2(h2u(h0), h2u(h1));
        }
    }

    const int ntiles = (N + 127) >> 7;
    const int gsz    = gridDim.x;

    const int sr  = tid >> 3;
    const int cof = (tid & 7) * 16;

    const uint32_t stS = sb + SM_STAGE + sr * STGB + cof;
    const char*    stC = smem + SM_STAGE + sr * STGB + cof;
    char*          xd0 = smem + SM_X0 + sr * SXB + cof / 2;

    const uint32_t aB = sb + SM_X0 + (wm + (lane & 15)) * SXB + (lane >> 4) * 16;
    const uint32_t bB = sb + SM_W  + (wn + (lane & 15)) * SXB + (lane >> 4) * 16;

    // ---- prologue: fetch t0, convert into X[0], fetch t1 ----
    {
        int t0 = blockIdx.x;
        if (t0 < ntiles) {
            int gr = (t0 << 7) + sr; if (gr > N - 1) gr = N - 1;
            const char* gp = (const char*)(x + (size_t)gr * H) + cof;
            #pragma unroll
            for (int i = 0; i < 4; i++) cpasync16(stS + i * 128, gp + i * 128);
        }
        CP_COMMIT();
        CP_WAIT0();
        #pragma unroll
        for (int i = 0; i < 4; i++) {
            float4 v = *reinterpret_cast<const float4*>(stC + i * 128);
            __half2 h0 = __float22half2_rn(make_float2(v.x, v.y));
            __half2 h1 = __float22half2_rn(make_float2(v.z, v.w));
            *reinterpret_cast<uint2*>(xd0 + i * 64) = make_uint2(h2u(h0), h2u(h1));
        }
        __syncthreads();
        int t1 = t0 + gsz;
        if (t1 < ntiles) {
            int gr = (t1 << 7) + sr; if (gr > N - 1) gr = N - 1;
            const char* gp = (const char*)(x + (size_t)gr * H) + cof;
            #pragma unroll
            for (int i = 0; i < 4; i++) cpasync16(stS + i * 128, gp + i * 128);
        }
        CP_COMMIT();
    }

    int cur = 0;
    for (int t = blockIdx.x; t < ntiles; t += gsz) {
        const int row0 = t << 7;

        CP_WAIT0();

        char* xdn = xd0 + (cur ^ 1) * XBUF;

        float acc[2][4][4];
        #pragma unroll
        for (int mt = 0; mt < 2; mt++)
            #pragma unroll
            for (int nt = 0; nt < 4; nt++)
                #pragma unroll
                for (int j = 0; j < 4; j++) acc[mt][nt][j] = 0.f;

        const uint32_t aT = aB + cur * XBUF;
        #pragma unroll
        for (int ks = 0; ks < 8; ks++) {
            if (ks < 4) {
                float4 v = *reinterpret_cast<const float4*>(stC + ks * 128);
                __half2 h0 = __float22half2_rn(make_float2(v.x, v.y));
                __half2 h1 = __float22half2_rn(make_float2(v.z, v.w));
                *reinterpret_cast<uint2*>(xdn + ks * 64) = make_uint2(h2u(h0), h2u(h1));
            }
            const uint32_t ko = ks * 32;
            uint32_t a0[4], a1[4], b0[4], b1[4];
            ldmx4(a0, aT + ko);
            ldmx4(a1, aT + 16 * SXB + ko);
            ldmx4(b0, bB + ko);
            ldmx4(b1, bB + 16 * SXB + ko);
            mma_f32(acc[0][0], a0, b0[0], b0[2]);
            mma_f32(acc[0][1], a0, b0[1], b0[3]);
            mma_f32(acc[0][2], a0, b1[0], b1[2]);
            mma_f32(acc[0][3], a0, b1[1], b1[3]);
            mma_f32(acc[1][0], a1, b0[0], b0[2]);
            mma_f32(acc[1][1], a1, b0[1], b0[3]);
            mma_f32(acc[1][2], a1, b1[0], b1[2]);
            mma_f32(acc[1][3], a1, b1[1], b1[3]);
        }

        __syncthreads();

        // ---- prefetch stage <- tile t+2 (overlaps epilogue) ----
        {
            int nt2 = t + 2 * gsz;
            if (nt2 < ntiles) {
                int gr = (nt2 << 7) + sr; if (gr > N - 1) gr = N - 1;
                const char* gp = (const char*)(x + (size_t)gr * H) + cof;
                #pragma unroll
                for (int i = 0; i < 4; i++) cpasync16(stS + i * 128, gp + i * 128);
            }
            CP_COMMIT();
        }

        // ---- epilogue: stage halves into X[cur] (dead), coalesced STG ----
        const bool self_half = (wn < H);
        const int cb2 = (self_half ? wn : wn - H) + (lane & 3) * 2;
        char* stage = smem + SM_X0 + cur * XBUF;

        #pragma unroll
        for (int hp = 0; hp < 2; hp++) {
            if (hp) __syncthreads();
            if (self_half == (hp == 0)) {
                #pragma unroll
                for (int mt = 0; mt < 2; mt++) {
                    const int rr = wm + mt * 16 + (lane >> 2);
                    #pragma unroll
                    for (int nt = 0; nt < 4; nt++) {
                        const int cc = cb2 + nt * 8;
                        float2 v0 = make_float2(acc[mt][nt][0], acc[mt][nt][1]);
                        float2 v1 = make_float2(acc[mt][nt][2], acc[mt][nt][3]);
                        if (self_half) {
                            float2 b2 = *(const float2*)&s_bias[cc];
                            v0.x += b2.x; v0.y += b2.y;
                            v1.x += b2.x; v1.y += b2.y;
                        }
                        *(__half2*)(stage + rr * SXB + cc * 2)       = __float22half2_rn(v0);
                        *(__half2*)(stage + (rr + 8) * SXB + cc * 2) = __float22half2_rn(v1);
                    }
                }
            }
            __syncthreads();
            // cooperative coalesced store: 128 rows x 256B; thread -> 32B
            {
                const int r  = tid >> 3;
                const int ch = (tid & 7) * 32;
                const int grow = row0 + r;
                if (grow < N) {
                    uint4 d0 = *(const uint4*)(stage + r * SXB + ch);
                    uint4 d1 = *(const uint4*)(stage + r * SXB + ch + 16);
                    __half* gb = hp ? g_y : g_acc;
                    char* dst = (char*)(gb + (size_t)grow * H) + ch;
                    *(uint4*)dst        = d0;
                    *(uint4*)(dst + 16) = d1;
                }
            }
        }
        __syncthreads();

        cur ^= 1;
    }
}

// ---------------------------------------------------------------------------
// CSR build
// ---------------------------------------------------------------------------
__global__ __launch_bounds__(512)
void hist_kernel(const int* __restrict__ ei, int E) {
    int i = blockIdx.x * 512 + threadIdx.x;
    int stride = gridDim.x * 512;
    for (int e = i; e < E; e += stride)
        atomicAdd(&g_deg[ei[E + e]], 1);
}

__global__ __launch_bounds__(256)
void assign_kernel(int N) {
    const int n    = blockIdx.x * 256 + threadIdx.x;
    const int lane = threadIdx.x & 31;
    int d = (n < N) ? g_deg[n] : 0;
    int s = d;
    #pragma unroll
    for (int o = 1; o < 32; o <<= 1) {
        int t = __shfl_up_sync(0xffffffffu, s, o);
        if (lane >= o) s += t;
    }
    int base = 0;
    if (lane == 31) base = atomicAdd(&g_total, s);
    base = __shfl_sync(0xffffffffu, base, 31);
    if (n < N) {
        int st = base + s - d;
        g_start[n]  = st;
        g_cursor[n] = st;
    }
}

__global__ __launch_bounds__(512)
void fill_kernel(const int* __restrict__ ei, const int* __restrict__ et, int E) {
    int i = blockIdx.x * 512 + threadIdx.x;
    int stride = gridDim.x * 512;
    for (int e = i; e < E; e += stride) {
        int src = ei[e];
        int dst = ei[E + e];
        int ty  = et[e];
        int slot = atomicAdd(&g_cursor[dst], 1);
        g_pk[slot] = src | (ty << 24);
    }
}

// ---------------------------------------------------------------------------
// Fused aggregate + ReLU + LayerNorm: one HALF-WARP (16 lanes) per node row.
// Cache policy: g_acc/g_pk evict-first; g_y default cached; out streaming.
// ---------------------------------------------------------------------------
__global__ __launch_bounds__(256)
void aggregate_ln_kernel(const float* __restrict__ gamma, const float* __restrict__ beta,
                         float* __restrict__ out, int N) {
    __shared__ float s_emb[NTYPES * H];
    for (int i = threadIdx.x; i < NTYPES * H; i += 256) s_emb[i] = g_emb2[i];
    __syncthreads();

    const int lane16 = threadIdx.x & 15;
    const int row    = blockIdx.x * 16 + (threadIdx.x >> 4);
    if (row >= N) return;
    const int off = lane16 * 8;    // 8 halves

    float v[8];
    {
        uint4 a = ldcs16(&g_acc[(size_t)row * H + off]);
        float2 f0 = __half22float2(u2h(a.x)), f1 = __half22float2(u2h(a.y));
        float2 f2 = __half22float2(u2h(a.z)), f3 = __half22float2(u2h(a.w));
        v[0] = f0.x; v[1] = f0.y; v[2] = f1.x; v[3] = f1.y;
        v[4] = f2.x; v[5] = f2.y; v[6] = f3.x; v[7] = f3.y;
    }

    const int st = __ldg(&g_start[row]);
    const int en = st + __ldg(&g_deg[row]);
    int i = st;
    for (; i + 2 <= en; i += 2) {
        int p0 = ldcs_i(&g_pk[i]), p1 = ldcs_i(&g_pk[i + 1]);
        int s0 = p0 & 0xFFFFFF, t0 = p0 >> 24;
        int s1 = p1 & 0xFFFFFF, t1 = p1 >> 24;
        uint4 m0 = __ldg((const uint4*)&g_y[(size_t)s0 * H + off]);
        uint4 m1 = __ldg((const uint4*)&g_y[(size_t)s1 * H + off]);
        float4 e0a = *(const float4*)&s_emb[t0 * H + off];
        float4 e0b = *(const float4*)&s_emb[t0 * H + off + 4];
        float4 e1a = *(const float4*)&s_emb[t1 * H + off];
        float4 e1b = *(const float4*)&s_emb[t1 * H + off + 4];
        float2 a0 = __half22float2(u2h(m0.x)), a1 = __half22float2(u2h(m0.y));
        float2 a2 = __half22float2(u2h(m0.z)), a3 = __half22float2(u2h(m0.w));
        float2 b0 = __half22float2(u2h(m1.x)), b1 = __half22float2(u2h(m1.y));
        float2 b2 = __half22float2(u2h(m1.z)), b3 = __half22float2(u2h(m1.w));
        v[0] += a0.x + e0a.x + b0.x + e1a.x;
        v[1] += a0.y + e0a.y + b0.y + e1a.y;
        v[2] += a1.x + e0a.z + b1.x + e1a.z;
        v[3] += a1.y + e0a.w + b1.y + e1a.w;
        v[4] += a2.x + e0b.x + b2.x + e1b.x;
        v[5] += a2.y + e0b.y + b2.y + e1b.y;
        v[6] += a3.x + e0b.z + b3.x + e1b.z;
        v[7] += a3.y + e0b.w + b3.y + e1b.w;
    }
    if (i < en) {
        int p0 = ldcs_i(&g_pk[i]);
        int s0 = p0 & 0xFFFFFF, t0 = p0 >> 24;
        uint4 m0 = __ldg((const uint4*)&g_y[(size_t)s0 * H + off]);
        float4 e0a = *(const float4*)&s_emb[t0 * H + off];
        float4 e0b = *(const float4*)&s_emb[t0 * H + off + 4];
        float2 a0 = __half22float2(u2h(m0.x)), a1 = __half22float2(u2h(m0.y));
        float2 a2 = __half22float2(u2h(m0.z)), a3 = __half22float2(u2h(m0.w));
        v[0] += a0.x + e0a.x; v[1] += a0.y + e0a.y;
        v[2] += a1.x + e0a.z; v[3] += a1.y + e0a.w;
        v[4] += a2.x + e0b.x; v[5] += a2.y + e0b.y;
        v[6] += a3.x + e0b.z; v[7] += a3.y + e0b.w;
    }

    float s = 0.f, sq = 0.f;
    #pragma unroll
    for (int j = 0; j < 8; j++) {
        v[j] = fmaxf(v[j], 0.f);
        s  += v[j];
        sq += v[j] * v[j];
    }
    #pragma unroll
    for (int o = 8; o > 0; o >>= 1) {
        s  += __shfl_xor_sync(0xffffffffu, s,  o);
        sq += __shfl_xor_sync(0xffffffffu, sq, o);
    }
    float mean = s * (1.f / H);
    float var  = sq * (1.f / H) - mean * mean;
    float rstd = rsqrtf(var + 1e-5f);

    float4 ga = *(const float4*)&gamma[off];
    float4 gb = *(const float4*)&gamma[off + 4];
    float4 ba = *(const float4*)&beta[off];
    float4 bb = *(const float4*)&beta[off + 4];
    float4 o0, o1;
    o0.x = (v[0] - mean) * rstd * ga.x + ba.x;
    o0.y = (v[1] - mean) * rstd * ga.y + ba.y;
    o0.z = (v[2] - mean) * rstd * ga.z + ba.z;
    o0.w = (v[3] - mean) * rstd * ga.w + ba.w;
    o1.x = (v[4] - mean) * rstd * gb.x + bb.x;
    o1.y = (v[5] - mean) * rstd * gb.y + bb.y;
    o1.z = (v[6] - mean) * rstd * gb.z + bb.z;
    o1.w = (v[7] - mean) * rstd * gb.w + bb.w;
    stcs16f(&out[(size_t)row * H + off],     o0);
    stcs16f(&out[(size_t)row * H + off + 4], o1);
}

// ---------------------------------------------------------------------------
extern "C" void kernel_launch(void* const* d_in, const int* in_sizes, int n_in,
                              void* d_out, int out_size) {
    const float* x     = (const float*)d_in[0];
    const int*   ei    = (const int*)  d_in[1];
    const int*   et    = (const int*)  d_in[2];
    const float* emb   = (const float*)d_in[3];
    const float* Wself = (const float*)d_in[4];
    const float* bself = (const float*)d_in[5];
    const float* Wmsg  = (const float*)d_in[6];
    const float* bmsg  = (const float*)d_in[7];
    const float* gamma = (const float*)d_in[8];
    const float* beta  = (const float*)d_in[9];
    float* out = (float*)d_out;

    const int N = in_sizes[0] / H;
    const int E = in_sizes[1] / 2;

    cudaFuncSetAttribute(gemm_tc_kernel, cudaFuncAttributeMaxDynamicSharedMemorySize, SM_TOT);

    // gemm_tc_kernel kept at absolute launch index 3 (the slot ncu samples).
    init_kernel<<<(N + 1023) / 1024, 1024>>>(emb, Wmsg, N);
    hist_kernel<<<592, 512>>>(ei, E);
    assign_kernel<<<(N + 255) / 256, 256>>>(N);
    gemm_tc_kernel<<<152, 1024, SM_TOT>>>(x, Wself, Wmsg, bself, bmsg, N);
    fill_kernel<<<592, 512>>>(ei, et, E);
    aggregate_ln_kernel<<<(N + 15) / 16, 256>>>(gamma, beta, out, N);
}